// round 6
// baseline (speedup 1.0000x reference)
#include <cuda_runtime.h>

#define NSEQ 12800
#define TSTEPS 512
#define CHUNK_T 8
#define NCHUNK (TSTEPS / CHUNK_T)

typedef unsigned long long u64;

// ---------- packed f32x2 + fast-math helpers ----------
__device__ __forceinline__ u64 pk2(float lo, float hi) {
    u64 u; asm("mov.b64 %0, {%1,%2};" : "=l"(u) : "f"(lo), "f"(hi)); return u;
}
__device__ __forceinline__ float2 upk2(u64 u) {
    float2 v; asm("mov.b64 {%0,%1}, %2;" : "=f"(v.x), "=f"(v.y) : "l"(u)); return v;
}
__device__ __forceinline__ u64 ffma2(u64 a, u64 b, u64 c) {
    u64 d; asm("fma.rn.f32x2 %0, %1, %2, %3;" : "=l"(d) : "l"(a), "l"(b), "l"(c)); return d;
}
__device__ __forceinline__ float tanh_a(float x) {
    float r; asm("tanh.approx.f32 %0, %1;" : "=f"(r) : "f"(x)); return r;
}
__device__ __forceinline__ float hsum(u64 a) { float2 v = upk2(a); return v.x + v.y; }

// volatile 16B smem load -> two packed f32x2 (prevents ptxas hoisting weights to regs)
__device__ __forceinline__ void lds_w2(u64& a, u64& b, unsigned addr) {
    asm volatile("ld.volatile.shared.v2.u64 {%0,%1}, [%2];"
                 : "=l"(a), "=l"(b) : "r"(addr));
}

// r/z gate weights pre-scaled by 0.5: sigmoid(x) = 0.5*tanh(x/2) + 0.5  (1 MUFU)
#define KRZ (0.5f)

// ---------- global scratch: ping-pong activation buffers, layout (T, N, 16) ----------
__device__ float g_bufA[(size_t)TSTEPS * NSEQ * 16];
__device__ float g_bufB[(size_t)TSTEPS * NSEQ * 16];

// ---------- cp.async chunk loader ----------
// smem chunk layout: [tt (CHUNK_T)][scan (16)][INF floats, row padded +16B]
template <int INF, bool RAW>
__device__ __forceinline__ void issue_chunk(char* sbuf, const float* __restrict__ x_in,
                                            int nb, int c, int dir, int tid) {
    constexpr int SCAN_STRIDE = INF * 4 + 16;
    constexpr int TT_STRIDE = 16 * SCAN_STRIDE;
    constexpr int V_PER_SCAN = INF / 4;               // 16B vectors per scan row
    constexpr int PER_TT = 16 * V_PER_SCAN;
    constexpr int TOTAL = CHUNK_T * PER_TT;
#pragma unroll
    for (int k = 0; k < TOTAL / 128; k++) {
        int j = k * 128 + tid;
        int tt = j / PER_TT;
        int r = j % PER_TT;
        int scan = r / V_PER_SCAN;
        int c16 = r % V_PER_SCAN;
        int t = dir ? (TSTEPS - 1 - (c * CHUNK_T + tt)) : (c * CHUNK_T + tt);
        const float* g = RAW
            ? x_in + (size_t)(nb + scan) * 4096 + (size_t)t * 8 + c16 * 4
            : x_in + ((size_t)t * NSEQ + (size_t)(nb + scan)) * 16 + c16 * 4;
        unsigned s = (unsigned)__cvta_generic_to_shared(
            sbuf + tt * TT_STRIDE + scan * SCAN_STRIDE + c16 * 16);
        asm volatile("cp.async.cg.shared.global [%0], [%1], 16;" :: "r"(s), "l"(g));
    }
}

// One bidirectional-GRU layer. Block = 128 threads = 16 scans (one direction).
// 8 lanes per scan; lane u owns hidden unit u (gate rows u, u+8, u+16).
// x staged via double-buffered cp.async smem; x-projection weights live in
// padded smem (volatile per-step reload, bank-conflict-free broadcast);
// h-weights + biases in registers. HEAD (layer 3): fwd only, no stores;
// fused 1-step bwd GRU at t=T-1 (h0=0) + lin1/LeakyReLU/lin2 head.
template <int INF, bool RAW_IN, bool HEAD>
__global__ void __launch_bounds__(128, 6)
gru_layer_kernel(const float* __restrict__ x_in, float* __restrict__ x_out,
                 const float* __restrict__ Wih, const float* __restrict__ Whh,
                 const float* __restrict__ bih, const float* __restrict__ bhh,
                 int wih_stride,
                 const float* __restrict__ l1w, const float* __restrict__ l1b,
                 const float* __restrict__ l2w, const float* __restrict__ l2b,
                 float* __restrict__ out)
{
    constexpr int IN_PAIRS = INF / 2;
    constexpr int SCAN_STRIDE = INF * 4 + 16;
    constexpr int TT_STRIDE = 16 * SCAN_STRIDE;
    constexpr int CHUNK_BYTES = CHUNK_T * TT_STRIDE;
    constexpr int WSTR = (INF == 16) ? 20 : 12;       // padded row stride (floats)

    extern __shared__ char sb[];
    float* ws = reinterpret_cast<float*>(sb + 2 * CHUNK_BYTES);   // 24 rows x WSTR

    const int tid = threadIdx.x;
    const int dir = HEAD ? 0 : (blockIdx.x / (NSEQ / 16));
    const int nb  = (HEAD ? blockIdx.x : (blockIdx.x % (NSEQ / 16))) * 16;
    const int u = tid & 7;
    const int scan_local = (tid >> 5) * 4 + ((tid >> 3) & 3);
    const int n = nb + scan_local;

    const float* wih = Wih + dir * wih_stride;
    const float* whh = Whh + dir * 192;
    const float* bi  = bih + dir * 24;
    const float* bh  = bhh + dir * 24;

    // ---- stage pre-scaled x-projection weights into smem (rows 0..15: *0.5) ----
    for (int idx = tid; idx < 24 * INF; idx += 128) {
        int row = idx / INF, col = idx % INF;
        float s = (row < 16) ? KRZ : 1.0f;
        ws[row * WSTR + col] = s * wih[row * INF + col];
    }

    // ---- h-weights + biases in registers ----
    u64 ur[4], uz[4], un[4];
#pragma unroll
    for (int p = 0; p < 4; p++) {
        ur[p] = pk2(KRZ * whh[(u     ) * 8 + 2 * p], KRZ * whh[(u     ) * 8 + 2 * p + 1]);
        uz[p] = pk2(KRZ * whh[(u +  8) * 8 + 2 * p], KRZ * whh[(u +  8) * 8 + 2 * p + 1]);
        un[p] = pk2(       whh[(u + 16) * 8 + 2 * p],        whh[(u + 16) * 8 + 2 * p + 1]);
    }
    const u64 brp  = pk2(KRZ * (bi[u]     + bh[u]),     0.0f);
    const u64 bzp  = pk2(KRZ * (bi[u + 8] + bh[u + 8]), 0.0f);
    const u64 bnxp = pk2(bi[u + 16], 0.0f);
    const u64 bnhp = pk2(bh[u + 16], 0.0f);

    // smem addresses for this lane's weight rows
    const unsigned ws_addr = (unsigned)__cvta_generic_to_shared(ws);
    const unsigned wrb = ws_addr + (u     ) * WSTR * 4;
    const unsigned wzb = ws_addr + (u +  8) * WSTR * 4;
    const unsigned wnb = ws_addr + (u + 16) * WSTR * 4;

    const int t0 = dir ? (TSTEPS - 1) : 0;
    float* op = HEAD ? nullptr
                     : (x_out + ((size_t)t0 * NSEQ + (size_t)n) * 16 + dir * 8 + u);
    const ptrdiff_t ostep = (ptrdiff_t)NSEQ * 16 * (dir ? -1 : 1);

    // ---- prime the pipeline ----
    issue_chunk<INF, RAW_IN>(sb, x_in, nb, 0, dir, tid);
    asm volatile("cp.async.commit_group;" ::: "memory");
    issue_chunk<INF, RAW_IN>(sb + CHUNK_BYTES, x_in, nb, 1, dir, tid);
    asm volatile("cp.async.commit_group;" ::: "memory");

    float h = 0.0f;

#pragma unroll 1
    for (int c = 0; c < NCHUNK; c++) {
        asm volatile("cp.async.wait_group 1;" ::: "memory");
        __syncthreads();
        const char* xrow = sb + (c & 1) * CHUNK_BYTES + scan_local * SCAN_STRIDE;

#pragma unroll
        for (int tt = 0; tt < CHUNK_T; tt++) {
            const ulonglong2* q = reinterpret_cast<const ulonglong2*>(xrow + tt * TT_STRIDE);
            u64 xc[IN_PAIRS];
#pragma unroll
            for (int i = 0; i < IN_PAIRS / 2; i++) {
                ulonglong2 v = q[i];
                xc[2 * i] = v.x; xc[2 * i + 1] = v.y;
            }

            // broadcast h[0..7] of this scan group (8 independent shfl)
            u64 hp[4];
#pragma unroll
            for (int p = 0; p < 4; p++) {
                float lo = __shfl_sync(0xffffffffu, h, 2 * p,     8);
                float hi = __shfl_sync(0xffffffffu, h, 2 * p + 1, 8);
                hp[p] = pk2(lo, hi);
            }

            u64 ar = brp, az = bzp, axn = bnxp, ahn = bnhp;
            // x-projection with smem-resident weights (volatile reload per step)
#pragma unroll
            for (int i = 0; i < IN_PAIRS / 2; i++) {
                u64 wa, wb;
                lds_w2(wa, wb, wrb + i * 16);
                ar = ffma2(wa, xc[2 * i], ar);
                ar = ffma2(wb, xc[2 * i + 1], ar);
                lds_w2(wa, wb, wzb + i * 16);
                az = ffma2(wa, xc[2 * i], az);
                az = ffma2(wb, xc[2 * i + 1], az);
                lds_w2(wa, wb, wnb + i * 16);
                axn = ffma2(wa, xc[2 * i], axn);
                axn = ffma2(wb, xc[2 * i + 1], axn);
            }
            // h-recurrence with register weights
#pragma unroll
            for (int p = 0; p < 4; p++) {
                ar  = ffma2(ur[p], hp[p], ar);
                az  = ffma2(uz[p], hp[p], az);
                ahn = ffma2(un[p], hp[p], ahn);
            }
            float r = fmaf(0.5f, tanh_a(hsum(ar)), 0.5f);   // sigmoid
            float z = fmaf(0.5f, tanh_a(hsum(az)), 0.5f);   // sigmoid
            float nn = tanh_a(fmaf(r, hsum(ahn), hsum(axn)));
            h = fmaf(z, h - nn, nn);

            if (!HEAD) { *op = h; op += ostep; }
        }
        __syncthreads();
        if (c + 2 < NCHUNK)
            issue_chunk<INF, RAW_IN>(sb + (c & 1) * CHUNK_BYTES, x_in, nb, c + 2, dir, tid);
        asm volatile("cp.async.commit_group;" ::: "memory");
    }

    if (HEAD) {
        // x[T-1] still resident in the last chunk's smem buffer
        const char* xrow = sb + ((NCHUNK - 1) & 1) * CHUNK_BYTES
                         + scan_local * SCAN_STRIDE + (CHUNK_T - 1) * TT_STRIDE;
        const ulonglong2* q = reinterpret_cast<const ulonglong2*>(xrow);
        u64 xc[IN_PAIRS];
#pragma unroll
        for (int i = 0; i < IN_PAIRS / 2; i++) {
            ulonglong2 v = q[i];
            xc[2 * i] = v.x; xc[2 * i + 1] = v.y;
        }

        // backward-direction single step at t=T-1, h0=0 (gh = b_hh); one-time
        // global weight reads (latency irrelevant here)
        const float* wihB = Wih + wih_stride;
        const float* biB  = bih + 24;
        const float* bhB  = bhh + 24;
        u64 ar = pk2(KRZ * (biB[u]     + bhB[u]),     0.0f);
        u64 az = pk2(KRZ * (biB[u + 8] + bhB[u + 8]), 0.0f);
        u64 ax = pk2(biB[u + 16], 0.0f);
        const float bnhB = bhB[u + 16];
#pragma unroll
        for (int p = 0; p < IN_PAIRS; p++) {
            u64 wrB = pk2(KRZ * wihB[(u     ) * INF + 2 * p], KRZ * wihB[(u     ) * INF + 2 * p + 1]);
            u64 wzB = pk2(KRZ * wihB[(u +  8) * INF + 2 * p], KRZ * wihB[(u +  8) * INF + 2 * p + 1]);
            u64 wnB = pk2(       wihB[(u + 16) * INF + 2 * p],        wihB[(u + 16) * INF + 2 * p + 1]);
            ar = ffma2(wrB, xc[p], ar);
            az = ffma2(wzB, xc[p], az);
            ax = ffma2(wnB, xc[p], ax);
        }
        float r = fmaf(0.5f, tanh_a(hsum(ar)), 0.5f);
        float z = fmaf(0.5f, tanh_a(hsum(az)), 0.5f);
        float nn = tanh_a(fmaf(r, bnhB, hsum(ax)));
        float hb = (1.0f - z) * nn;   // h0 = 0

        // head: lin1 + LeakyReLU(0.2) + lin2 over [h_f ; h_b]
        float mid = l1b[u];
#pragma unroll
        for (int cc = 0; cc < 8; cc++) {
            float hf_c = __shfl_sync(0xffffffffu, h,  cc, 8);
            float hb_c = __shfl_sync(0xffffffffu, hb, cc, 8);
            mid = fmaf(l1w[u * 16 + cc],     hf_c, mid);
            mid = fmaf(l1w[u * 16 + 8 + cc], hb_c, mid);
        }
        float act = (mid >= 0.0f) ? mid : 0.2f * mid;

        float o = l2b[u];
#pragma unroll
        for (int cc = 0; cc < 8; cc++) {
            float a_c = __shfl_sync(0xffffffffu, act, cc, 8);
            o = fmaf(l2w[u * 8 + cc], a_c, o);
        }
        out[(size_t)n * 8 + u] = o;
    }
}

extern "C" void kernel_launch(void* const* d_in, const int* in_sizes, int n_in,
                              void* d_out, int out_size) {
    (void)in_sizes; (void)n_in; (void)out_size;
    const float* raw  = (const float*)d_in[0];
    const float* Wih0 = (const float*)d_in[1];
    const float* Whh0 = (const float*)d_in[2];
    const float* bih0 = (const float*)d_in[3];
    const float* bhh0 = (const float*)d_in[4];
    const float* WihR = (const float*)d_in[5];   // (3, 2, 24, 16)
    const float* WhhR = (const float*)d_in[6];   // (3, 2, 24, 8)
    const float* bihR = (const float*)d_in[7];   // (3, 2, 24)
    const float* bhhR = (const float*)d_in[8];   // (3, 2, 24)
    const float* l1w  = (const float*)d_in[9];
    const float* l1b  = (const float*)d_in[10];
    const float* l2w  = (const float*)d_in[11];
    const float* l2b  = (const float*)d_in[12];
    float* out = (float*)d_out;

    float *bufA, *bufB;
    cudaGetSymbolAddress((void**)&bufA, g_bufA);
    cudaGetSymbolAddress((void**)&bufB, g_bufB);

    const int BLK_FULL = 2 * (NSEQ / 16);   // 1600 blocks (fwd + bwd)
    const int BLK_HEAD = NSEQ / 16;         // 800 blocks (fwd only)
    const int SMEM8  = 2 * CHUNK_T * 16 * (8 * 4 + 16)  + 24 * 12 * 4;  // 13440
    const int SMEM16 = 2 * CHUNK_T * 16 * (16 * 4 + 16) + 24 * 20 * 4;  // 22400

    // Layer 0: raw -> bufA
    gru_layer_kernel<8, true, false><<<BLK_FULL, 128, SMEM8>>>(
        raw, bufA, Wih0, Whh0, bih0, bhh0, 192,
        nullptr, nullptr, nullptr, nullptr, nullptr);

    // Layer 1: bufA -> bufB
    gru_layer_kernel<16, false, false><<<BLK_FULL, 128, SMEM16>>>(
        bufA, bufB, WihR + 0 * 768, WhhR + 0 * 384, bihR + 0 * 48, bhhR + 0 * 48, 384,
        nullptr, nullptr, nullptr, nullptr, nullptr);

    // Layer 2: bufB -> bufA
    gru_layer_kernel<16, false, false><<<BLK_FULL, 128, SMEM16>>>(
        bufB, bufA, WihR + 1 * 768, WhhR + 1 * 384, bihR + 1 * 48, bhhR + 1 * 48, 384,
        nullptr, nullptr, nullptr, nullptr, nullptr);

    // Layer 3 + head: bufA -> out
    gru_layer_kernel<16, false, true><<<BLK_HEAD, 128, SMEM16>>>(
        bufA, nullptr, WihR + 2 * 768, WhhR + 2 * 384, bihR + 2 * 48, bhhR + 2 * 48, 384,
        l1w, l1b, l2w, l2b, out);
}

// round 7
// speedup vs baseline: 1.9073x; 1.9073x over previous
#include <cuda_runtime.h>

#define NSEQ 12800
#define TSTEPS 512
#define CHUNK_T 8
#define NCHUNK (TSTEPS / CHUNK_T)

typedef unsigned long long u64;

// ---------- packed f32x2 + fast-math helpers ----------
__device__ __forceinline__ u64 pk2(float lo, float hi) {
    u64 u; asm("mov.b64 %0, {%1,%2};" : "=l"(u) : "f"(lo), "f"(hi)); return u;
}
__device__ __forceinline__ float2 upk2(u64 u) {
    float2 v; asm("mov.b64 {%0,%1}, %2;" : "=f"(v.x), "=f"(v.y) : "l"(u)); return v;
}
__device__ __forceinline__ u64 ffma2(u64 a, u64 b, u64 c) {
    u64 d; asm("fma.rn.f32x2 %0, %1, %2, %3;" : "=l"(d) : "l"(a), "l"(b), "l"(c)); return d;
}
__device__ __forceinline__ float tanh_a(float x) {
    float r; asm("tanh.approx.f32 %0, %1;" : "=f"(r) : "f"(x)); return r;
}
__device__ __forceinline__ float hsum(u64 a) { float2 v = upk2(a); return v.x + v.y; }

// r/z gate weights pre-scaled by 0.5: sigmoid(x) = 0.5*tanh(x/2) + 0.5  (1 MUFU)
#define KRZ (0.5f)

// ---------- global scratch: ping-pong activation buffers, layout (T, N, 16) ----------
__device__ float g_bufA[(size_t)TSTEPS * NSEQ * 16];
__device__ float g_bufB[(size_t)TSTEPS * NSEQ * 16];

// ---------- per-WARP cp.async chunk loader (no block barriers anywhere) ----------
// warp-private chunk layout: [tt (CHUNK_T)][scan (4)][INF floats + 16B pad]
template <int INF, bool RAW>
__device__ __forceinline__ void issue_chunk_w(char* dst, const float* __restrict__ x_in,
                                              int n0, int c, int dir, int lane) {
    constexpr int VPS = INF / 4;                 // 16B vectors per scan row
    constexpr int ROW_B = INF * 4 + 16;
    constexpr int TT_B = 4 * ROW_B;
    constexpr int PER_TT = 4 * VPS;
    constexpr int TOTAL = CHUNK_T * PER_TT;      // 128 (INF=16) / 64 (INF=8)
#pragma unroll
    for (int k = 0; k < TOTAL / 32; k++) {
        int j = k * 32 + lane;
        int tt = j / PER_TT;
        int r = j % PER_TT;
        int scan = r / VPS;
        int c16 = r % VPS;
        int t = dir ? (TSTEPS - 1 - (c * CHUNK_T + tt)) : (c * CHUNK_T + tt);
        const float* g = RAW
            ? x_in + (size_t)(n0 + scan) * 4096 + (size_t)t * 8 + c16 * 4
            : x_in + ((size_t)t * NSEQ + (size_t)(n0 + scan)) * 16 + c16 * 4;
        unsigned s = (unsigned)__cvta_generic_to_shared(dst + tt * TT_B + scan * ROW_B + c16 * 16);
        asm volatile("cp.async.cg.shared.global [%0], [%1], 16;" :: "r"(s), "l"(g));
    }
}

// One bidirectional-GRU layer. Each WARP owns 4 scans of one direction and
// free-runs: private double-buffered cp.async x-ring, no __syncthreads, so
// warps de-phase and interleave each other's dependency chains.
// 8 lanes per scan; lane u owns hidden unit u (gate rows u, u+8, u+16).
// All weights in registers. HEAD (layer 3): fwd only, no stores; fused 1-step
// bwd GRU at t=T-1 (h0=0) + lin1/LeakyReLU(0.2)/lin2 head.
template <int INF, bool RAW_IN, bool HEAD>
__global__ void __launch_bounds__(128, 4)
gru_layer_kernel(const float* __restrict__ x_in, float* __restrict__ x_out,
                 const float* __restrict__ Wih, const float* __restrict__ Whh,
                 const float* __restrict__ bih, const float* __restrict__ bhh,
                 int wih_stride,
                 const float* __restrict__ l1w, const float* __restrict__ l1b,
                 const float* __restrict__ l2w, const float* __restrict__ l2b,
                 float* __restrict__ out)
{
    constexpr int IN_PAIRS = INF / 2;
    constexpr int ROW_B = INF * 4 + 16;
    constexpr int TT_B = 4 * ROW_B;
    constexpr int CHUNK_B = CHUNK_T * TT_B;
    constexpr int WARP_B = 2 * CHUNK_B;

    extern __shared__ char sb[];

    const int tid = threadIdx.x;
    const int wid = tid >> 5;
    const int lane = tid & 31;
    const int u = tid & 7;
    const int sg = (tid >> 3) & 3;               // scan within warp
    const int warpG = blockIdx.x * 4 + wid;
    const int dir = HEAD ? 0 : (warpG / (NSEQ / 4));
    const int wi  = HEAD ? warpG : (warpG % (NSEQ / 4));
    const int n0 = wi * 4;
    const int n = n0 + sg;
    char* wsb = sb + wid * WARP_B;               // this warp's private ring

    // ---- register weights, pre-scaled ----
    const float* wih = Wih + dir * wih_stride;
    const float* whh = Whh + dir * 192;
    const float* bi  = bih + dir * 24;
    const float* bh  = bhh + dir * 24;

    u64 wr[IN_PAIRS], wz[IN_PAIRS], wn[IN_PAIRS];
#pragma unroll
    for (int p = 0; p < IN_PAIRS; p++) {
        wr[p] = pk2(KRZ * wih[(u     ) * INF + 2 * p], KRZ * wih[(u     ) * INF + 2 * p + 1]);
        wz[p] = pk2(KRZ * wih[(u +  8) * INF + 2 * p], KRZ * wih[(u +  8) * INF + 2 * p + 1]);
        wn[p] = pk2(       wih[(u + 16) * INF + 2 * p],        wih[(u + 16) * INF + 2 * p + 1]);
    }
    u64 ur[4], uz[4], un[4];
#pragma unroll
    for (int p = 0; p < 4; p++) {
        ur[p] = pk2(KRZ * whh[(u     ) * 8 + 2 * p], KRZ * whh[(u     ) * 8 + 2 * p + 1]);
        uz[p] = pk2(KRZ * whh[(u +  8) * 8 + 2 * p], KRZ * whh[(u +  8) * 8 + 2 * p + 1]);
        un[p] = pk2(       whh[(u + 16) * 8 + 2 * p],        whh[(u + 16) * 8 + 2 * p + 1]);
    }
    const u64 brp  = pk2(KRZ * (bi[u]     + bh[u]),     0.0f);
    const u64 bzp  = pk2(KRZ * (bi[u + 8] + bh[u + 8]), 0.0f);
    const u64 bnxp = pk2(bi[u + 16], 0.0f);
    const u64 bnhp = pk2(bh[u + 16], 0.0f);

    const int t0 = dir ? (TSTEPS - 1) : 0;
    float* op = HEAD ? nullptr
                     : (x_out + ((size_t)t0 * NSEQ + (size_t)n) * 16 + dir * 8 + u);
    const ptrdiff_t ostep = (ptrdiff_t)NSEQ * 16 * (dir ? -1 : 1);

    // ---- prime the per-warp pipeline ----
    issue_chunk_w<INF, RAW_IN>(wsb, x_in, n0, 0, dir, lane);
    asm volatile("cp.async.commit_group;" ::: "memory");
    issue_chunk_w<INF, RAW_IN>(wsb + CHUNK_B, x_in, n0, 1, dir, lane);
    asm volatile("cp.async.commit_group;" ::: "memory");

    float h = 0.0f;

#pragma unroll 1
    for (int c = 0; c < NCHUNK; c++) {
        asm volatile("cp.async.wait_group 1;" ::: "memory");
        __syncwarp();
        const char* xbase = wsb + (c & 1) * CHUNK_B + sg * ROW_B;

#pragma unroll
        for (int tt = 0; tt < CHUNK_T; tt++) {
            const ulonglong2* q = reinterpret_cast<const ulonglong2*>(xbase + tt * TT_B);

            // broadcast h[0..7] of this scan group first (cover shfl latency
            // with the independent x-projection below)
            u64 hp[4];
#pragma unroll
            for (int p = 0; p < 4; p++) {
                float lo = __shfl_sync(0xffffffffu, h, 2 * p,     8);
                float hi = __shfl_sync(0xffffffffu, h, 2 * p + 1, 8);
                hp[p] = pk2(lo, hi);
            }

            u64 ar = brp, az = bzp, axn = bnxp, ahn = bnhp;
            // x-projection in blocks of 4 pairs (limits xc register footprint)
#pragma unroll
            for (int blk = 0; blk < IN_PAIRS / 4; blk++) {
                ulonglong2 va = q[2 * blk];
                ulonglong2 vb = q[2 * blk + 1];
                ar  = ffma2(wr[4 * blk + 0], va.x, ar);
                az  = ffma2(wz[4 * blk + 0], va.x, az);
                axn = ffma2(wn[4 * blk + 0], va.x, axn);
                ar  = ffma2(wr[4 * blk + 1], va.y, ar);
                az  = ffma2(wz[4 * blk + 1], va.y, az);
                axn = ffma2(wn[4 * blk + 1], va.y, axn);
                ar  = ffma2(wr[4 * blk + 2], vb.x, ar);
                az  = ffma2(wz[4 * blk + 2], vb.x, az);
                axn = ffma2(wn[4 * blk + 2], vb.x, axn);
                ar  = ffma2(wr[4 * blk + 3], vb.y, ar);
                az  = ffma2(wz[4 * blk + 3], vb.y, az);
                axn = ffma2(wn[4 * blk + 3], vb.y, axn);
            }
            // h-recurrence
#pragma unroll
            for (int p = 0; p < 4; p++) {
                ar  = ffma2(ur[p], hp[p], ar);
                az  = ffma2(uz[p], hp[p], az);
                ahn = ffma2(un[p], hp[p], ahn);
            }
            float r = fmaf(0.5f, tanh_a(hsum(ar)), 0.5f);   // sigmoid
            float z = fmaf(0.5f, tanh_a(hsum(az)), 0.5f);   // sigmoid
            float nn = tanh_a(fmaf(r, hsum(ahn), hsum(axn)));
            h = fmaf(z, h - nn, nn);

            if (!HEAD) { *op = h; op += ostep; }
        }
        // refill the buffer this warp just finished consuming (warp-sequential,
        // no cross-warp sharing -> no block barrier needed)
        if (c + 2 < NCHUNK)
            issue_chunk_w<INF, RAW_IN>(wsb + (c & 1) * CHUNK_B, x_in, n0, c + 2, dir, lane);
        asm volatile("cp.async.commit_group;" ::: "memory");
    }

    if (HEAD) {
        // x[T-1] still resident in the last chunk's buffer
        const char* xrow = wsb + ((NCHUNK - 1) & 1) * CHUNK_B
                         + sg * ROW_B + (CHUNK_T - 1) * TT_B;
        const ulonglong2* q = reinterpret_cast<const ulonglong2*>(xrow);

        // backward-direction single step at t=T-1, h0=0 (gh = b_hh)
        const float* wihB = Wih + wih_stride;
        const float* biB  = bih + 24;
        const float* bhB  = bhh + 24;
        u64 ar = pk2(KRZ * (biB[u]     + bhB[u]),     0.0f);
        u64 az = pk2(KRZ * (biB[u + 8] + bhB[u + 8]), 0.0f);
        u64 ax = pk2(biB[u + 16], 0.0f);
        const float bnhB = bhB[u + 16];
#pragma unroll
        for (int p = 0; p < IN_PAIRS; p++) {
            u64 xcp = reinterpret_cast<const u64*>(q)[p];
            u64 wrB = pk2(KRZ * wihB[(u     ) * INF + 2 * p], KRZ * wihB[(u     ) * INF + 2 * p + 1]);
            u64 wzB = pk2(KRZ * wihB[(u +  8) * INF + 2 * p], KRZ * wihB[(u +  8) * INF + 2 * p + 1]);
            u64 wnB = pk2(       wihB[(u + 16) * INF + 2 * p],        wihB[(u + 16) * INF + 2 * p + 1]);
            ar = ffma2(wrB, xcp, ar);
            az = ffma2(wzB, xcp, az);
            ax = ffma2(wnB, xcp, ax);
        }
        float r = fmaf(0.5f, tanh_a(hsum(ar)), 0.5f);
        float z = fmaf(0.5f, tanh_a(hsum(az)), 0.5f);
        float nn = tanh_a(fmaf(r, bnhB, hsum(ax)));
        float hb = (1.0f - z) * nn;   // h0 = 0

        // head: lin1 + LeakyReLU(0.2) + lin2 over [h_f ; h_b]
        float mid = l1b[u];
#pragma unroll
        for (int cc = 0; cc < 8; cc++) {
            float hf_c = __shfl_sync(0xffffffffu, h,  cc, 8);
            float hb_c = __shfl_sync(0xffffffffu, hb, cc, 8);
            mid = fmaf(l1w[u * 16 + cc],     hf_c, mid);
            mid = fmaf(l1w[u * 16 + 8 + cc], hb_c, mid);
        }
        float act = (mid >= 0.0f) ? mid : 0.2f * mid;

        float o = l2b[u];
#pragma unroll
        for (int cc = 0; cc < 8; cc++) {
            float a_c = __shfl_sync(0xffffffffu, act, cc, 8);
            o = fmaf(l2w[u * 8 + cc], a_c, o);
        }
        out[(size_t)n * 8 + u] = o;
    }
}

extern "C" void kernel_launch(void* const* d_in, const int* in_sizes, int n_in,
                              void* d_out, int out_size) {
    (void)in_sizes; (void)n_in; (void)out_size;
    const float* raw  = (const float*)d_in[0];
    const float* Wih0 = (const float*)d_in[1];
    const float* Whh0 = (const float*)d_in[2];
    const float* bih0 = (const float*)d_in[3];
    const float* bhh0 = (const float*)d_in[4];
    const float* WihR = (const float*)d_in[5];   // (3, 2, 24, 16)
    const float* WhhR = (const float*)d_in[6];   // (3, 2, 24, 8)
    const float* bihR = (const float*)d_in[7];   // (3, 2, 24)
    const float* bhhR = (const float*)d_in[8];   // (3, 2, 24)
    const float* l1w  = (const float*)d_in[9];
    const float* l1b  = (const float*)d_in[10];
    const float* l2w  = (const float*)d_in[11];
    const float* l2b  = (const float*)d_in[12];
    float* out = (float*)d_out;

    float *bufA, *bufB;
    cudaGetSymbolAddress((void**)&bufA, g_bufA);
    cudaGetSymbolAddress((void**)&bufB, g_bufB);

    const int BLK_FULL = 2 * (NSEQ / 16);   // 1600 blocks (fwd + bwd)
    const int BLK_HEAD = NSEQ / 16;         // 800 blocks (fwd only)
    const int SMEM8  = 4 * 2 * CHUNK_T * 4 * (8 * 4 + 16);    // 12288
    const int SMEM16 = 4 * 2 * CHUNK_T * 4 * (16 * 4 + 16);   // 20480

    // Layer 0: raw -> bufA
    gru_layer_kernel<8, true, false><<<BLK_FULL, 128, SMEM8>>>(
        raw, bufA, Wih0, Whh0, bih0, bhh0, 192,
        nullptr, nullptr, nullptr, nullptr, nullptr);

    // Layer 1: bufA -> bufB
    gru_layer_kernel<16, false, false><<<BLK_FULL, 128, SMEM16>>>(
        bufA, bufB, WihR + 0 * 768, WhhR + 0 * 384, bihR + 0 * 48, bhhR + 0 * 48, 384,
        nullptr, nullptr, nullptr, nullptr, nullptr);

    // Layer 2: bufB -> bufA
    gru_layer_kernel<16, false, false><<<BLK_FULL, 128, SMEM16>>>(
        bufB, bufA, WihR + 1 * 768, WhhR + 1 * 384, bihR + 1 * 48, bhhR + 1 * 48, 384,
        nullptr, nullptr, nullptr, nullptr, nullptr);

    // Layer 3 + head: bufA -> out
    gru_layer_kernel<16, false, true><<<BLK_HEAD, 128, SMEM16>>>(
        bufA, nullptr, WihR + 2 * 768, WhhR + 2 * 384, bihR + 2 * 48, bhhR + 2 * 48, 384,
        l1w, l1b, l2w, l2b, out);
}